// round 3
// baseline (speedup 1.0000x reference)
#include <cuda_runtime.h>
#include <math.h>

#define MTOT 32768          // B * N = 8 * 4096
#define DD   512
#define BB   8
#define NTOK 4096
#define HH   64

// ---------------- scratch (static device globals; no runtime allocation) ----
__device__ float g_z[(size_t)MTOT * 1536];   // pre-activations [m][3*512]
__device__ float g_lam[(size_t)DD * MTOT];   // [d][m]
__device__ float g_inp[(size_t)DD * MTOT];   // [d][m]
__device__ float g_gate[(size_t)DD * MTOT];  // [d][m]
__device__ float g_hid[(size_t)DD * MTOT];   // [d][m]
__device__ float g_scale[MTOT];

// ---------------- K1: Z = x @ [Win | Wf | Wg]  (M=32768, K=512, N=1536) -----
__global__ __launch_bounds__(256, 2) void k1_gemm(
    const float* __restrict__ x,
    const float* __restrict__ Win,
    const float* __restrict__ Wf,
    const float* __restrict__ Wg)
{
    __shared__ float As[2][8][128];
    __shared__ float Bs[2][8][128];
    const int bn0 = blockIdx.x * 128;
    const int bm0 = blockIdx.y * 128;
    const int sec = bn0 >> 9;                     // which weight (uniform per block)
    const float* Wp = (sec == 0) ? Win : ((sec == 1) ? Wf : Wg);
    const int nb = bn0 & 511;
    const int tid = threadIdx.x;

    const int a_row = tid >> 1;                   // 0..127
    const int a_col = (tid & 1) << 2;             // 0 or 4
    const int b_row = tid >> 5;                   // 0..7
    const int b_col = (tid & 31) << 2;            // 0..124
    const float* Aptr = x + (size_t)(bm0 + a_row) * 512 + a_col;
    const float* Bptr = Wp + (size_t)b_row * 512 + nb + b_col;
    const int tx = tid & 15, ty = tid >> 4;

    float acc[8][8];
#pragma unroll
    for (int i = 0; i < 8; i++)
#pragma unroll
        for (int j = 0; j < 8; j++) acc[i][j] = 0.f;

    float4 av = *(const float4*)Aptr;
    float4 bv = *(const float4*)Bptr;
    As[0][a_col + 0][a_row] = av.x; As[0][a_col + 1][a_row] = av.y;
    As[0][a_col + 2][a_row] = av.z; As[0][a_col + 3][a_row] = av.w;
    *(float4*)&Bs[0][b_row][b_col] = bv;
    __syncthreads();

    int buf = 0;
    for (int k0 = 0; k0 < 512; k0 += 8) {
        const bool more = (k0 + 8) < 512;
        if (more) {
            av = *(const float4*)(Aptr + k0 + 8);
            bv = *(const float4*)(Bptr + (size_t)(k0 + 8) * 512);
        }
#pragma unroll
        for (int kk = 0; kk < 8; kk++) {
            float a[8], b[8];
            *(float4*)&a[0] = *(const float4*)&As[buf][kk][ty * 4];
            *(float4*)&a[4] = *(const float4*)&As[buf][kk][64 + ty * 4];
            *(float4*)&b[0] = *(const float4*)&Bs[buf][kk][tx * 4];
            *(float4*)&b[4] = *(const float4*)&Bs[buf][kk][64 + tx * 4];
#pragma unroll
            for (int i = 0; i < 8; i++)
#pragma unroll
                for (int j = 0; j < 8; j++) acc[i][j] += a[i] * b[j];
        }
        if (more) {
            buf ^= 1;
            As[buf][a_col + 0][a_row] = av.x; As[buf][a_col + 1][a_row] = av.y;
            As[buf][a_col + 2][a_row] = av.z; As[buf][a_col + 3][a_row] = av.w;
            *(float4*)&Bs[buf][b_row][b_col] = bv;
            __syncthreads();
        }
    }
#pragma unroll
    for (int i = 0; i < 8; i++) {
        const int m = bm0 + ((i < 4) ? (ty * 4 + i) : (64 + ty * 4 + i - 4));
        float* orow = g_z + (size_t)m * 1536 + bn0;
        *(float4*)&orow[tx * 4]      = make_float4(acc[i][0], acc[i][1], acc[i][2], acc[i][3]);
        *(float4*)&orow[64 + tx * 4] = make_float4(acc[i][4], acc[i][5], acc[i][6], acc[i][7]);
    }
}

// ---------------- K2: activations + transpose to [d][m] ---------------------
__global__ void k2_act(const float* __restrict__ b_in,
                       const float* __restrict__ b_f,
                       const float* __restrict__ b_g,
                       const float* __restrict__ lb)
{
    __shared__ float sl[32][33], si[32][33], sg[32][33];
    const int m0 = blockIdx.x * 32, d0 = blockIdx.y * 32;
    const int tx = threadIdx.x, ty = threadIdx.y;   // 32 x 8
    const float lbv = lb[0];
#pragma unroll
    for (int r = 0; r < 4; r++) {
        const int m = m0 + ty + r * 8;
        const int d = d0 + tx;
        const float* zr = g_z + (size_t)m * 1536;
        const float zi = zr[d]        + b_in[d];
        const float zf = zr[512 + d]  + b_f[d];
        const float zg = zr[1024 + d] + b_g[d];
        const float u   = zi / (1.f + expf(-zi));                 // silu
        const float lam = lbv + (1.f - lbv) / (1.f + expf(-zf));  // bounded decay
        sl[ty + r * 8][tx] = lam;
        si[ty + r * 8][tx] = (1.f - lam) * u;
        sg[ty + r * 8][tx] = 1.f / (1.f + expf(-zg));
    }
    __syncthreads();
#pragma unroll
    for (int r = 0; r < 4; r++) {
        const int d = d0 + ty + r * 8;
        const int m = m0 + tx;
        const size_t o = (size_t)d * MTOT + m;
        g_lam[o]  = sl[tx][ty + r * 8];
        g_inp[o]  = si[tx][ty + r * 8];
        g_gate[o] = sg[tx][ty + r * 8];
    }
}

// ---------------- K3: 4-direction complex gated scan on 64x64 tile ----------
// One block per (d, b). smem pad 65 -> conflict-free row AND column access.
__global__ void k3_scan(const float* __restrict__ theta)
{
    extern __shared__ float sm[];
    float* sl = sm;                 // 64*65
    float* si = sm + 64 * 65;       // 64*65
    float* sh = sm + 2 * 64 * 65;   // 64*65
    const int d = blockIdx.x;
    const int b = blockIdx.y;
    const size_t base = (size_t)d * MTOT + (size_t)b * NTOK;
    const int t = threadIdx.x;      // 0..63

#pragma unroll 8
    for (int i = t; i < 4096; i += 64) {
        const int r = i >> 6, c = i & 63;
        sl[r * 65 + c] = g_lam[base + i];
        si[r * 65 + c] = g_inp[base + i];
        sh[r * 65 + c] = 0.f;
    }
    const float th = theta[d];
    const float cth = cosf(th), sth = sinf(th);
    __syncthreads();

    // axis 1 (over c within row t): forward then backward
    {
        const float* lrow = sl + t * 65;
        const float* irow = si + t * 65;
        float* hrow = sh + t * 65;
        float hr = 0.f, hi = 0.f;
        for (int s2 = 0; s2 < 64; s2++) {
            const float lam = lrow[s2];
            const float lc = lam * cth, ls = lam * sth;
            const float nr = lc * hr - ls * hi + irow[s2];
            hi = ls * hr + lc * hi;
            hr = nr;
            hrow[s2] += hr;
        }
        hr = 0.f; hi = 0.f;
        for (int s2 = 63; s2 >= 0; s2--) {
            const float lam = lrow[s2];
            const float lc = lam * cth, ls = lam * sth;
            const float nr = lc * hr - ls * hi + irow[s2];
            hi = ls * hr + lc * hi;
            hr = nr;
            hrow[s2] += hr;
        }
    }
    __syncthreads();
    // axis 0 (over r within column t): forward then backward
    {
        float hr = 0.f, hi = 0.f;
        for (int s2 = 0; s2 < 64; s2++) {
            const float lam = sl[s2 * 65 + t];
            const float lc = lam * cth, ls = lam * sth;
            const float nr = lc * hr - ls * hi + si[s2 * 65 + t];
            hi = ls * hr + lc * hi;
            hr = nr;
            sh[s2 * 65 + t] += hr;
        }
        hr = 0.f; hi = 0.f;
        for (int s2 = 63; s2 >= 0; s2--) {
            const float lam = sl[s2 * 65 + t];
            const float lc = lam * cth, ls = lam * sth;
            const float nr = lc * hr - ls * hi + si[s2 * 65 + t];
            hi = ls * hr + lc * hi;
            hr = nr;
            sh[s2 * 65 + t] += hr;
        }
    }
    __syncthreads();
#pragma unroll 8
    for (int i = t; i < 4096; i += 64) {
        const int r = i >> 6, c = i & 63;
        g_hid[base + i] = sh[r * 65 + c];
    }
}

// ---------------- K4: per-row RMS scale -------------------------------------
__global__ void k4_scale()
{
    const int m = blockIdx.x * 256 + threadIdx.x;
    float acc = 0.f;
#pragma unroll 8
    for (int d = 0; d < 512; d++) {
        const float v = g_hid[(size_t)d * MTOT + m];
        acc += v * v;
    }
    g_scale[m] = rsqrtf(acc * (1.f / 512.f) + 1e-6f);
}

// ---------------- K5: Y = (g .* hid .* scale) @ Wout + bout -----------------
// A is stored K-major ([d][m]) -> direct coalesced float4 A-tile loads.
__global__ __launch_bounds__(256, 2) void k5_gemm(
    const float* __restrict__ Wout,
    const float* __restrict__ bout,
    float* __restrict__ out)
{
    __shared__ float As[2][8][128];
    __shared__ float Bs[2][8][128];
    const int bn0 = blockIdx.x * 128;
    const int bm0 = blockIdx.y * 128;
    const int tid = threadIdx.x;

    const int ak = tid >> 5;                 // k row 0..7
    const int am = (tid & 31) << 2;          // m offset 0..124
    const int b_row = tid >> 5;
    const int b_col = (tid & 31) << 2;
    const float* Bptr = Wout + (size_t)b_row * 512 + bn0 + b_col;
    const int tx = tid & 15, ty = tid >> 4;

    const float4 sv = *(const float4*)&g_scale[bm0 + am];

    float acc[8][8];
#pragma unroll
    for (int i = 0; i < 8; i++)
#pragma unroll
        for (int j = 0; j < 8; j++) acc[i][j] = 0.f;

    float4 hv = *(const float4*)&g_hid[(size_t)ak * MTOT + bm0 + am];
    float4 gv = *(const float4*)&g_gate[(size_t)ak * MTOT + bm0 + am];
    float4 bv = *(const float4*)Bptr;
    As[0][ak][am + 0] = hv.x * gv.x * sv.x;
    As[0][ak][am + 1] = hv.y * gv.y * sv.y;
    As[0][ak][am + 2] = hv.z * gv.z * sv.z;
    As[0][ak][am + 3] = hv.w * gv.w * sv.w;
    *(float4*)&Bs[0][b_row][b_col] = bv;
    __syncthreads();

    int buf = 0;
    for (int k0 = 0; k0 < 512; k0 += 8) {
        const bool more = (k0 + 8) < 512;
        if (more) {
            hv = *(const float4*)&g_hid [(size_t)(k0 + 8 + ak) * MTOT + bm0 + am];
            gv = *(const float4*)&g_gate[(size_t)(k0 + 8 + ak) * MTOT + bm0 + am];
            bv = *(const float4*)(Bptr + (size_t)(k0 + 8) * 512);
        }
#pragma unroll
        for (int kk = 0; kk < 8; kk++) {
            float a[8], b[8];
            *(float4*)&a[0] = *(const float4*)&As[buf][kk][ty * 4];
            *(float4*)&a[4] = *(const float4*)&As[buf][kk][64 + ty * 4];
            *(float4*)&b[0] = *(const float4*)&Bs[buf][kk][tx * 4];
            *(float4*)&b[4] = *(const float4*)&Bs[buf][kk][64 + tx * 4];
#pragma unroll
            for (int i = 0; i < 8; i++)
#pragma unroll
                for (int j = 0; j < 8; j++) acc[i][j] += a[i] * b[j];
        }
        if (more) {
            buf ^= 1;
            As[buf][ak][am + 0] = hv.x * gv.x * sv.x;
            As[buf][ak][am + 1] = hv.y * gv.y * sv.y;
            As[buf][ak][am + 2] = hv.z * gv.z * sv.z;
            As[buf][ak][am + 3] = hv.w * gv.w * sv.w;
            *(float4*)&Bs[buf][b_row][b_col] = bv;
            __syncthreads();
        }
    }

    const float4 bo0 = *(const float4*)&bout[bn0 + tx * 4];
    const float4 bo1 = *(const float4*)&bout[bn0 + 64 + tx * 4];
#pragma unroll
    for (int i = 0; i < 8; i++) {
        const int m = bm0 + ((i < 4) ? (ty * 4 + i) : (64 + ty * 4 + i - 4));
        float* orow = out + (size_t)m * 512 + bn0;
        *(float4*)&orow[tx * 4] = make_float4(acc[i][0] + bo0.x, acc[i][1] + bo0.y,
                                              acc[i][2] + bo0.z, acc[i][3] + bo0.w);
        *(float4*)&orow[64 + tx * 4] = make_float4(acc[i][4] + bo1.x, acc[i][5] + bo1.y,
                                                   acc[i][6] + bo1.z, acc[i][7] + bo1.w);
    }
}

// ---------------- launch ----------------------------------------------------
extern "C" void kernel_launch(void* const* d_in, const int* in_sizes, int n_in,
                              void* d_out, int out_size)
{
    const float* x    = (const float*)d_in[0];
    const float* lb   = (const float*)d_in[1];
    const float* Win  = (const float*)d_in[2];
    const float* bin  = (const float*)d_in[3];
    const float* Wf   = (const float*)d_in[4];
    const float* bf   = (const float*)d_in[5];
    const float* th   = (const float*)d_in[6];
    const float* Wg   = (const float*)d_in[7];
    const float* bg   = (const float*)d_in[8];
    const float* Wout = (const float*)d_in[9];
    const float* bout = (const float*)d_in[10];
    float* out = (float*)d_out;

    k1_gemm<<<dim3(12, 256), 256>>>(x, Win, Wf, Wg);
    k2_act<<<dim3(MTOT / 32, DD / 32), dim3(32, 8)>>>(bin, bf, bg, lb);

    const int scan_smem = 3 * 64 * 65 * 4;   // 49,920 B > 48 KB -> opt-in
    cudaFuncSetAttribute(k3_scan, cudaFuncAttributeMaxDynamicSharedMemorySize, scan_smem);
    k3_scan<<<dim3(DD, BB), 64, scan_smem>>>(th);

    k4_scale<<<MTOT / 256, 256>>>();
    k5_gemm<<<dim3(4, 256), 256>>>(Wout, bout, out);
}

// round 7
// speedup vs baseline: 1.8687x; 1.8687x over previous
#include <cuda_runtime.h>
#include <cuda_bf16.h>
#include <cstdint>
#include <math.h>

#define MTOT 32768          // B * N
#define DD   512
#define BB   8
#define NTOK 4096

// ---------------- scratch (static device globals) ---------------------------
__device__ __align__(16) __nv_bfloat16 g_xh[(size_t)MTOT * 512];
__device__ __align__(16) __nv_bfloat16 g_xl[(size_t)MTOT * 512];
__device__ __align__(16) __nv_bfloat16 g_wth[1536 * 512];   // [n][k] of [Win|Wf|Wg]
__device__ __align__(16) __nv_bfloat16 g_wtl[1536 * 512];
__device__ __align__(16) __nv_bfloat16 g_woth[512 * 512];   // [n][k] of Wout
__device__ __align__(16) __nv_bfloat16 g_wotl[512 * 512];
__device__ float g_lam[(size_t)DD * MTOT];    // [d][m]
__device__ float g_u[(size_t)DD * MTOT];      // silu(z_in)  [d][m]
__device__ float g_gate[(size_t)DD * MTOT];   // [d][m]
__device__ float g_hid[(size_t)DD * MTOT];    // [d][m]
__device__ float g_scale[MTOT];
__device__ __align__(16) __nv_bfloat16 g_ah[(size_t)MTOT * 512];  // k5 A hi [m][k]
__device__ __align__(16) __nv_bfloat16 g_al[(size_t)MTOT * 512];

// ---------------- helpers ----------------------------------------------------
__device__ __forceinline__ uint32_t smem_u32(const void* p) {
    uint32_t a;
    asm("{ .reg .u64 t; cvta.to.shared.u64 t, %1; cvt.u32.u64 %0, t; }" : "=r"(a) : "l"(p));
    return a;
}
__device__ __forceinline__ void cp16(uint32_t s, const void* g) {
    asm volatile("cp.async.cg.shared.global [%0], [%1], 16;" :: "r"(s), "l"(g));
}
__device__ __forceinline__ void ldsm4(uint32_t* r, uint32_t addr) {
    asm volatile("ldmatrix.sync.aligned.m8n8.x4.shared.b16 {%0,%1,%2,%3}, [%4];"
                 : "=r"(r[0]), "=r"(r[1]), "=r"(r[2]), "=r"(r[3]) : "r"(addr));
}
__device__ __forceinline__ void mma_bf16(float* c, const uint32_t* a,
                                         uint32_t b0, uint32_t b1) {
    asm volatile("mma.sync.aligned.m16n8k16.row.col.f32.bf16.bf16.f32 "
                 "{%0,%1,%2,%3}, {%4,%5,%6,%7}, {%8,%9}, {%0,%1,%2,%3};"
                 : "+f"(c[0]), "+f"(c[1]), "+f"(c[2]), "+f"(c[3])
                 : "r"(a[0]), "r"(a[1]), "r"(a[2]), "r"(a[3]), "r"(b0), "r"(b1));
}
#define CP_COMMIT()  asm volatile("cp.async.commit_group;" ::: "memory")
#define CP_WAIT2()   asm volatile("cp.async.wait_group 2;" ::: "memory")
#define CP_WAIT0()   asm volatile("cp.async.wait_group 0;" ::: "memory")

#define STAGE_BYTES 32768
#define SMEM_BYTES  98304   // 3 stages; epilogue staging (128*132*4=67.6KB) reuses it

// ---------------- shared HMMA mainloop --------------------------------------
__device__ __forceinline__ void gemm_core(
    uint32_t sb,
    const __nv_bfloat16* __restrict__ Ah, const __nv_bfloat16* __restrict__ Al,
    const __nv_bfloat16* __restrict__ Bh, const __nv_bfloat16* __restrict__ Bl,
    int m0, int n0, float (&c)[4][4][4])
{
    const int tid = threadIdx.x, w = tid >> 5, l = tid & 31;
    const int wm = (w & 1) * 64, wn = (w >> 1) * 32;
    const int laneRow = l & 15;
    const int colsel = (l >> 4) & 1;

#pragma unroll
    for (int i = 0; i < 4; i++)
#pragma unroll
        for (int j = 0; j < 4; j++)
#pragma unroll
            for (int k = 0; k < 4; k++) c[i][j][k] = 0.f;

    auto issue = [&](int chunk, int stage) {
        const int kc = chunk * 32;
        const uint32_t s0 = sb + stage * STAGE_BYTES;
#pragma unroll
        for (int i = 0; i < 2; i++) {
            const int idx = tid + i * 256;          // 0..511
            const int row = idx >> 2, u = idx & 3;
            uint32_t off = row * 64 + u * 16;
            off ^= (off >> 3) & 0x30;               // SW64 swizzle
            const size_t ga = (size_t)(m0 + row) * 512 + kc + u * 8;
            const size_t gb = (size_t)(n0 + row) * 512 + kc + u * 8;
            cp16(s0 + off,         Ah + ga);
            cp16(s0 + 8192 + off,  Al + ga);
            cp16(s0 + 16384 + off, Bh + gb);
            cp16(s0 + 24576 + off, Bl + gb);
        }
        CP_COMMIT();
    };

    issue(0, 0); issue(1, 1); issue(2, 2);

    for (int cidx = 0; cidx < 16; cidx++) {
        if (cidx < 14) CP_WAIT2(); else CP_WAIT0();
        __syncthreads();
        const uint32_t s0 = sb + (cidx % 3) * STAGE_BYTES;
#pragma unroll
        for (int s = 0; s < 2; s++) {
            const int kb = s * 32 + colsel * 16;
            uint32_t ah[4][4], al[4][4], bh[2][4], bl[2][4];
#pragma unroll
            for (int i = 0; i < 4; i++) {
                uint32_t off = (wm + 16 * i + laneRow) * 64 + kb;
                off ^= (off >> 3) & 0x30;
                ldsm4(ah[i], s0 + off);
                ldsm4(al[i], s0 + 8192 + off);
            }
#pragma unroll
            for (int j = 0; j < 2; j++) {
                uint32_t off = (wn + 16 * j + laneRow) * 64 + kb;
                off ^= (off >> 3) & 0x30;
                ldsm4(bh[j], s0 + 16384 + off);
                ldsm4(bl[j], s0 + 24576 + off);
            }
#pragma unroll
            for (int mi = 0; mi < 4; mi++)
#pragma unroll
                for (int nj = 0; nj < 4; nj++) {
                    // ldmatrix.x4 on B tile: r0=(nLo,kLo) r1=(nHi,kLo) r2=(nLo,kHi) r3=(nHi,kHi)
                    // mma B fragment = {same-n kLo, same-n kHi}  ->  {r[h], r[2+h]}
                    const int h = nj & 1;
                    const int jt = nj >> 1;
                    mma_bf16(c[mi][nj], ah[mi], bh[jt][h], bh[jt][2 + h]);
                    mma_bf16(c[mi][nj], ah[mi], bl[jt][h], bl[jt][2 + h]);
                    mma_bf16(c[mi][nj], al[mi], bh[jt][h], bh[jt][2 + h]);
                }
        }
        __syncthreads();
        if (cidx + 3 < 16) issue(cidx + 3, cidx % 3);
    }
    CP_WAIT0();
    __syncthreads();
}

// ---------------- K0x: fp32 -> bf16 hi/lo split -----------------------------
__global__ void k0x(const float* __restrict__ x)
{
    const size_t i = ((size_t)blockIdx.x * 256 + threadIdx.x) * 4;
    const float4 v = *(const float4*)(x + i);
    __nv_bfloat16 h[4], l[4];
    h[0] = __float2bfloat16(v.x); l[0] = __float2bfloat16(v.x - __bfloat162float(h[0]));
    h[1] = __float2bfloat16(v.y); l[1] = __float2bfloat16(v.y - __bfloat162float(h[1]));
    h[2] = __float2bfloat16(v.z); l[2] = __float2bfloat16(v.z - __bfloat162float(h[2]));
    h[3] = __float2bfloat16(v.w); l[3] = __float2bfloat16(v.w - __bfloat162float(h[3]));
    *(uint2*)(g_xh + i) = *(uint2*)h;
    *(uint2*)(g_xl + i) = *(uint2*)l;
}

// ---------------- K0w: transpose + split weights ----------------------------
__global__ void k0w(const float* __restrict__ Win, const float* __restrict__ Wf,
                    const float* __restrict__ Wg)
{
    __shared__ float ts[32][33];
    const int n0 = blockIdx.x * 32, k0 = blockIdx.y * 32;
    const int tx = threadIdx.x, ty = threadIdx.y;
    const int sec = n0 >> 9;
    const float* W = (sec == 0) ? Win : ((sec == 1) ? Wf : Wg);
    const int nloc0 = n0 & 511;
#pragma unroll
    for (int r = 0; r < 4; r++)
        ts[ty + r * 8][tx] = W[(size_t)(k0 + ty + r * 8) * 512 + nloc0 + tx];
    __syncthreads();
#pragma unroll
    for (int r = 0; r < 4; r++) {
        const int n = n0 + ty + r * 8, k = k0 + tx;
        const float v = ts[tx][ty + r * 8];
        const __nv_bfloat16 hi = __float2bfloat16(v);
        g_wth[(size_t)n * 512 + k] = hi;
        g_wtl[(size_t)n * 512 + k] = __float2bfloat16(v - __bfloat162float(hi));
    }
}
__global__ void k0wo(const float* __restrict__ Wout)
{
    __shared__ float ts[32][33];
    const int n0 = blockIdx.x * 32, k0 = blockIdx.y * 32;
    const int tx = threadIdx.x, ty = threadIdx.y;
#pragma unroll
    for (int r = 0; r < 4; r++)
        ts[ty + r * 8][tx] = Wout[(size_t)(k0 + ty + r * 8) * 512 + n0 + tx];
    __syncthreads();
#pragma unroll
    for (int r = 0; r < 4; r++) {
        const int n = n0 + ty + r * 8, k = k0 + tx;
        const float v = ts[tx][ty + r * 8];
        const __nv_bfloat16 hi = __float2bfloat16(v);
        g_woth[(size_t)n * 512 + k] = hi;
        g_wotl[(size_t)n * 512 + k] = __float2bfloat16(v - __bfloat162float(hi));
    }
}

// ---------------- K1t: Z = x @ [Win|Wf|Wg], fused activation epilogue -------
__global__ __launch_bounds__(256) void k1t(
    const float* __restrict__ b_in, const float* __restrict__ b_f,
    const float* __restrict__ b_g, const float* __restrict__ lb)
{
    extern __shared__ char smem[];
    const uint32_t sb = smem_u32(smem);
    const int tid = threadIdx.x, w = tid >> 5, l = tid & 31;
    const int n0 = blockIdx.x * 128;      // 0..1535
    const int m0 = blockIdx.y * 128;

    float c[4][4][4];
    gemm_core(sb, g_xh, g_xl, g_wth, g_wtl, m0, n0, c);

    // stage C as [n][m] (pad 132) for coalesced [d][m] global writes
    float* sf = (float*)smem;
    {
        const int wm = (w & 1) * 64, wn = (w >> 1) * 32;
        const int mB = wm + (l >> 2), nB = wn + (l & 3) * 2;
#pragma unroll
        for (int mi = 0; mi < 4; mi++)
#pragma unroll
            for (int nj = 0; nj < 4; nj++) {
                const int m = mB + 16 * mi;
                const int n = nB + 8 * nj;
                sf[n * 132 + m]           = c[mi][nj][0];
                sf[(n + 1) * 132 + m]     = c[mi][nj][1];
                sf[n * 132 + m + 8]       = c[mi][nj][2];
                sf[(n + 1) * 132 + m + 8] = c[mi][nj][3];
            }
    }
    __syncthreads();

    const int sec = n0 >> 9;
    const int d0 = n0 & 511;
    const float lbv = lb[0];
    const float* bias = (sec == 0) ? b_in : ((sec == 1) ? b_f : b_g);
    const int nl = tid >> 1;                 // local n (d) row 0..127
    const int mh = (tid & 1) * 64;           // m half
    const int d = d0 + nl;
    const float bz = bias[d];
    float* gdst = (sec == 0) ? g_u : ((sec == 1) ? g_lam : g_gate);
    float* orow = gdst + (size_t)d * MTOT + m0 + mh;
    const float* srow = sf + nl * 132 + mh;
#pragma unroll
    for (int i = 0; i < 16; i++) {
        float4 v = *(const float4*)(srow + i * 4);
        float r4[4] = {v.x + bz, v.y + bz, v.z + bz, v.w + bz};
        float o4[4];
        if (sec == 0) {
#pragma unroll
            for (int q = 0; q < 4; q++) o4[q] = r4[q] / (1.f + __expf(-r4[q]));
        } else if (sec == 1) {
#pragma unroll
            for (int q = 0; q < 4; q++) o4[q] = lbv + (1.f - lbv) / (1.f + __expf(-r4[q]));
        } else {
#pragma unroll
            for (int q = 0; q < 4; q++) o4[q] = 1.f / (1.f + __expf(-r4[q]));
        }
        *(float4*)(orow + i * 4) = make_float4(o4[0], o4[1], o4[2], o4[3]);
    }
}

// ---------------- K3: 4-direction complex gated scan ------------------------
__global__ void k3_scan(const float* __restrict__ theta)
{
    extern __shared__ float sm[];
    float* sl = sm;
    float* si = sm + 64 * 65;
    float* sh = sm + 2 * 64 * 65;
    const int d = blockIdx.x, b = blockIdx.y;
    const size_t base = (size_t)d * MTOT + (size_t)b * NTOK;
    const int t = threadIdx.x;

#pragma unroll 8
    for (int i = t; i < 4096; i += 64) {
        const int r = i >> 6, c = i & 63;
        const float lam = g_lam[base + i];
        sl[r * 65 + c] = lam;
        si[r * 65 + c] = (1.f - lam) * g_u[base + i];
        sh[r * 65 + c] = 0.f;
    }
    const float th = theta[d];
    const float cth = cosf(th), sth = sinf(th);
    __syncthreads();
    {
        const float* lrow = sl + t * 65;
        const float* irow = si + t * 65;
        float* hrow = sh + t * 65;
        float hr = 0.f, hi = 0.f;
        for (int s2 = 0; s2 < 64; s2++) {
            const float lam = lrow[s2];
            const float lc = lam * cth, ls = lam * sth;
            const float nr = lc * hr - ls * hi + irow[s2];
            hi = ls * hr + lc * hi; hr = nr;
            hrow[s2] += hr;
        }
        hr = 0.f; hi = 0.f;
        for (int s2 = 63; s2 >= 0; s2--) {
            const float lam = lrow[s2];
            const float lc = lam * cth, ls = lam * sth;
            const float nr = lc * hr - ls * hi + irow[s2];
            hi = ls * hr + lc * hi; hr = nr;
            hrow[s2] += hr;
        }
    }
    __syncthreads();
    {
        float hr = 0.f, hi = 0.f;
        for (int s2 = 0; s2 < 64; s2++) {
            const float lam = sl[s2 * 65 + t];
            const float lc = lam * cth, ls = lam * sth;
            const float nr = lc * hr - ls * hi + si[s2 * 65 + t];
            hi = ls * hr + lc * hi; hr = nr;
            sh[s2 * 65 + t] += hr;
        }
        hr = 0.f; hi = 0.f;
        for (int s2 = 63; s2 >= 0; s2--) {
            const float lam = sl[s2 * 65 + t];
            const float lc = lam * cth, ls = lam * sth;
            const float nr = lc * hr - ls * hi + si[s2 * 65 + t];
            hi = ls * hr + lc * hi; hr = nr;
            sh[s2 * 65 + t] += hr;
        }
    }
    __syncthreads();
#pragma unroll 8
    for (int i = t; i < 4096; i += 64) {
        const int r = i >> 6, c = i & 63;
        g_hid[base + i] = sh[r * 65 + c];
    }
}

// ---------------- K4: per-row RMS scale -------------------------------------
__global__ __launch_bounds__(256) void k4_scale()
{
    __shared__ float4 sp[8][32];
    const int m0 = blockIdx.x * 128;
    const int w = threadIdx.x >> 5, l = threadIdx.x & 31;
    float4 acc = make_float4(0.f, 0.f, 0.f, 0.f);
    const float* p = g_hid + (size_t)(w * 64) * MTOT + m0 + l * 4;
#pragma unroll 8
    for (int d = 0; d < 64; d++) {
        const float4 v = *(const float4*)(p + (size_t)d * MTOT);
        acc.x += v.x * v.x; acc.y += v.y * v.y;
        acc.z += v.z * v.z; acc.w += v.w * v.w;
    }
    sp[w][l] = acc;
    __syncthreads();
    if (threadIdx.x < 32) {
        float4 s = sp[0][l];
#pragma unroll
        for (int w2 = 1; w2 < 8; w2++) {
            const float4 v = sp[w2][l];
            s.x += v.x; s.y += v.y; s.z += v.z; s.w += v.w;
        }
        float4 r;
        r.x = rsqrtf(s.x * (1.f / 512.f) + 1e-6f);
        r.y = rsqrtf(s.y * (1.f / 512.f) + 1e-6f);
        r.z = rsqrtf(s.z * (1.f / 512.f) + 1e-6f);
        r.w = rsqrtf(s.w * (1.f / 512.f) + 1e-6f);
        *(float4*)&g_scale[m0 + l * 4] = r;
    }
}

// ---------------- K5p: A = gate*hid*scale -> [m][k] bf16 split --------------
__global__ void k5p()
{
    __shared__ float ts[32][33];
    const int m0 = blockIdx.x * 32, d0 = blockIdx.y * 32;
    const int tx = threadIdx.x, ty = threadIdx.y;
#pragma unroll
    for (int r = 0; r < 4; r++) {
        const int d = d0 + ty + r * 8;
        const int m = m0 + tx;
        const size_t o = (size_t)d * MTOT + m;
        ts[ty + r * 8][tx] = g_gate[o] * g_hid[o] * g_scale[m];
    }
    __syncthreads();
#pragma unroll
    for (int r = 0; r < 4; r++) {
        const int m = m0 + ty + r * 8;
        const int d = d0 + tx;
        const float v = ts[tx][ty + r * 8];
        const __nv_bfloat16 hi = __float2bfloat16(v);
        g_ah[(size_t)m * 512 + d] = hi;
        g_al[(size_t)m * 512 + d] = __float2bfloat16(v - __bfloat162float(hi));
    }
}

// ---------------- K5t: Y = A @ Wout + bout ----------------------------------
__global__ __launch_bounds__(256) void k5t(const float* __restrict__ bout,
                                           float* __restrict__ out)
{
    extern __shared__ char smem[];
    const uint32_t sb = smem_u32(smem);
    const int tid = threadIdx.x, w = tid >> 5, l = tid & 31;
    const int n0 = blockIdx.x * 128;      // 0..511
    const int m0 = blockIdx.y * 128;

    float c[4][4][4];
    gemm_core(sb, g_ah, g_al, g_woth, g_wotl, m0, n0, c);

    // stage C as [m][n] (pad 132) for coalesced row writes
    float* sf = (float*)smem;
    {
        const int wm = (w & 1) * 64, wn = (w >> 1) * 32;
        const int mB = wm + (l >> 2), nB = wn + (l & 3) * 2;
#pragma unroll
        for (int mi = 0; mi < 4; mi++)
#pragma unroll
            for (int nj = 0; nj < 4; nj++) {
                const int m = mB + 16 * mi;
                const int n = nB + 8 * nj;
                sf[m * 132 + n]           = c[mi][nj][0];
                sf[m * 132 + n + 1]       = c[mi][nj][1];
                sf[(m + 8) * 132 + n]     = c[mi][nj][2];
                sf[(m + 8) * 132 + n + 1] = c[mi][nj][3];
            }
    }
    __syncthreads();

    const int ml = tid >> 1;
    const int nh = (tid & 1) * 64;
    const float* srow = sf + ml * 132 + nh;
    float* orow = out + (size_t)(m0 + ml) * 512 + n0 + nh;
    const float* brow = bout + n0 + nh;
#pragma unroll
    for (int i = 0; i < 16; i++) {
        float4 v = *(const float4*)(srow + i * 4);
        const float4 bo = *(const float4*)(brow + i * 4);
        *(float4*)(orow + i * 4) =
            make_float4(v.x + bo.x, v.y + bo.y, v.z + bo.z, v.w + bo.w);
    }
}

// ---------------- launch ----------------------------------------------------
extern "C" void kernel_launch(void* const* d_in, const int* in_sizes, int n_in,
                              void* d_out, int out_size)
{
    const float* x    = (const float*)d_in[0];
    const float* lb   = (const float*)d_in[1];
    const float* Win  = (const float*)d_in[2];
    const float* bin  = (const float*)d_in[3];
    const float* Wf   = (const float*)d_in[4];
    const float* bf   = (const float*)d_in[5];
    const float* th   = (const float*)d_in[6];
    const float* Wg   = (const float*)d_in[7];
    const float* bg   = (const float*)d_in[8];
    const float* Wout = (const float*)d_in[9];
    const float* bout = (const float*)d_in[10];
    float* out = (float*)d_out;

    cudaFuncSetAttribute(k1t, cudaFuncAttributeMaxDynamicSharedMemorySize, SMEM_BYTES);
    cudaFuncSetAttribute(k5t, cudaFuncAttributeMaxDynamicSharedMemorySize, SMEM_BYTES);
    const int scan_smem = 3 * 64 * 65 * 4;
    cudaFuncSetAttribute(k3_scan, cudaFuncAttributeMaxDynamicSharedMemorySize, scan_smem);

    k0x<<<16384, 256>>>(x);
    k0w<<<dim3(48, 16), dim3(32, 8)>>>(Win, Wf, Wg);
    k0wo<<<dim3(16, 16), dim3(32, 8)>>>(Wout);

    k1t<<<dim3(12, 256), 256, SMEM_BYTES>>>(bin, bf, bg, lb);

    k3_scan<<<dim3(DD, BB), 64, scan_smem>>>(th);
    k4_scale<<<256, 256>>>();
    k5p<<<dim3(MTOT / 32, 16), dim3(32, 8)>>>();

    k5t<<<dim3(4, 256), 256, SMEM_BYTES>>>(bout, out);
}